// round 7
// baseline (speedup 1.0000x reference)
#include <cuda_runtime.h>
#include <math.h>
#include <stdint.h>

// Problem-size maxima (fixed by the dataset: N=100000, E=1600000, F=H=128, OUT=40)
#define NMAX 100000
#define EMAX 1600000
#define FDIM 128

// ---------------- scratch (static device globals; no allocation) ----------------
__device__ __align__(16) float g_bufG[(size_t)NMAX * FDIM];   // h = A@W (unscaled)
__device__ __align__(16) float g_bufO[(size_t)NMAX * FDIM];   // out1, then s = out2+out1
__device__ float g_dinv[NMAX];
__device__ int   g_cnt[NMAX];
__device__ int   g_rowstart[NMAX + 1];
__device__ int   g_cursor[NMAX];
__device__ int   g_csrc[EMAX];

// ---------------- packed fp32x2 helpers (sm_103a FFMA2 path) ----------------
__device__ __forceinline__ unsigned long long pack2_dup(float x) {
    unsigned long long r;
    asm("mov.b64 %0, {%1, %1};" : "=l"(r) : "f"(x));
    return r;
}
__device__ __forceinline__ void fma2(unsigned long long& d,
                                     unsigned long long a,
                                     unsigned long long b) {
    asm("fma.rn.f32x2 %0, %1, %2, %0;" : "+l"(d) : "l"(a), "l"(b));
}

// ---------------- CSR build ----------------
__global__ void zero_cnt_kernel(int n) {
    int i = blockIdx.x * blockDim.x + threadIdx.x;
    if (i < n) g_cnt[i] = 0;
}

__global__ void count_kernel(const int* __restrict__ dst, int e) {
    int i = blockIdx.x * blockDim.x + threadIdx.x;
    if (i < e) atomicAdd(&g_cnt[dst[i]], 1);
}

// Single-block exclusive scan over counts -> rowstart/cursor; also dinv = rsqrt(cnt+1).
__global__ void scan_kernel(int n, int e_total) {
    __shared__ int sums[1024];
    int t = threadIdx.x;
    int chunk = (n + 1023) >> 10;
    int lo = t * chunk;
    int hi = lo + chunk; if (hi > n) hi = n;
    int s = 0;
    for (int i = lo; i < hi; i++) s += g_cnt[i];
    sums[t] = s;
    __syncthreads();
    for (int off = 1; off < 1024; off <<= 1) {
        int v = (t >= off) ? sums[t - off] : 0;
        __syncthreads();
        sums[t] += v;
        __syncthreads();
    }
    int prefix = (t == 0) ? 0 : sums[t - 1];
    for (int i = lo; i < hi; i++) {
        int c = g_cnt[i];
        g_rowstart[i] = prefix;
        g_cursor[i]   = prefix;
        g_dinv[i]     = rsqrtf((float)(c + 1));   // +1 self loop
        prefix += c;
    }
    if (t == 1023) g_rowstart[n] = e_total;
}

__global__ void place_kernel(const int* __restrict__ src, const int* __restrict__ dst, int e) {
    int i = blockIdx.x * blockDim.x + threadIdx.x;
    if (i < e) {
        int d = dst[i];
        int p = atomicAdd(&g_cursor[d], 1);
        g_csrc[p] = src[i];
    }
}

// ---------------- GEMM: C = A @ W;  A:[n,128], W:[128,128]  (pure GEMM) ----------------
// Tile: 128 rows x 128 cols, BK=16, 256 threads, 8x8 micro-tile per thread.
// Accumulators packed as fp32x2 column pairs -> FFMA2 (2x fp32 rate on sm_103a).
__global__ __launch_bounds__(256) void gemm_nk128(const float* __restrict__ A,
                                                  const float* __restrict__ W,
                                                  float* __restrict__ C, int n) {
    __shared__ float As[16][128];   // [k][row]  (transposed)
    __shared__ float Bs[16][128];   // [k][col]
    int m0 = blockIdx.x * 128;
    int t = threadIdx.x;
    int tr = (t >> 4) * 8;   // row offset of micro-tile
    int tc = (t & 15) * 8;   // col offset of micro-tile
    unsigned long long acc2[8][4];  // [row][col-pair], pair j = cols (tc+2j, tc+2j+1)
#pragma unroll
    for (int r = 0; r < 8; r++)
#pragma unroll
        for (int c = 0; c < 4; c++) acc2[r][c] = 0ULL;

    for (int k0 = 0; k0 < 128; k0 += 16) {
        // stage A tile: 128 rows x 16 k = 2048 floats (transpose on store)
#pragma unroll
        for (int j = 0; j < 2; j++) {
            int flat = t * 8 + j * 4;
            int row = flat >> 4, kk = flat & 15;
            float4 v = make_float4(0.f, 0.f, 0.f, 0.f);
            if (m0 + row < n)
                v = *(const float4*)(A + (size_t)(m0 + row) * 128 + k0 + kk);
            As[kk + 0][row] = v.x;
            As[kk + 1][row] = v.y;
            As[kk + 2][row] = v.z;
            As[kk + 3][row] = v.w;
        }
        // stage W tile: 16 k x 128 cols
#pragma unroll
        for (int j = 0; j < 2; j++) {
            int flat = t * 8 + j * 4;
            int kr = flat >> 7, cc = flat & 127;
            *(float4*)&Bs[kr][cc] = *(const float4*)(W + (size_t)(k0 + kr) * 128 + cc);
        }
        __syncthreads();
#pragma unroll
        for (int k = 0; k < 16; k++) {
            float4 a0 = *(float4*)&As[k][tr];
            float4 a1 = *(float4*)&As[k][tr + 4];
            ulonglong2 b0 = *(ulonglong2*)&Bs[k][tc];       // pairs (c0,c1),(c2,c3)
            ulonglong2 b1 = *(ulonglong2*)&Bs[k][tc + 4];   // pairs (c4,c5),(c6,c7)
            float a[8] = {a0.x, a0.y, a0.z, a0.w, a1.x, a1.y, a1.z, a1.w};
#pragma unroll
            for (int r = 0; r < 8; r++) {
                unsigned long long ar = pack2_dup(a[r]);
                fma2(acc2[r][0], ar, b0.x);
                fma2(acc2[r][1], ar, b0.y);
                fma2(acc2[r][2], ar, b1.x);
                fma2(acc2[r][3], ar, b1.y);
            }
        }
        __syncthreads();
    }
#pragma unroll
    for (int r = 0; r < 8; r++) {
        int row = m0 + tr + r;
        if (row < n) {
            ulonglong2 s0; s0.x = acc2[r][0]; s0.y = acc2[r][1];
            ulonglong2 s1; s1.x = acc2[r][2]; s1.y = acc2[r][3];
            *(ulonglong2*)(C + (size_t)row * 128 + tc)     = s0;
            *(ulonglong2*)(C + (size_t)row * 128 + tc + 4) = s1;
        }
    }
}

// ---------------- Aggregation: warp per node (pull / gather) ----------------
// O[i] = relu( dinv[i] * ( sum_j h[j]*dinv[j]  +  h[i]*dinv[i] ) + bias )  [+ resid[i]]
__global__ __launch_bounds__(256) void aggregate_kernel(const float* __restrict__ G,
                                                        const float* __restrict__ bias,
                                                        float* O, const float* resid,
                                                        int has_resid, int n) {
    int warp = (blockIdx.x * blockDim.x + threadIdx.x) >> 5;
    int lane = threadIdx.x & 31;
    if (warp >= n) return;
    int s = g_rowstart[warp];
    int e = g_rowstart[warp + 1];
    const float4* G4 = (const float4*)G;
    size_t self = (size_t)warp * 32 + lane;
    float d = g_dinv[warp];
    float4 sv = G4[self];                         // self loop: h[i]*dinv[i]
    float4 acc = make_float4(sv.x * d, sv.y * d, sv.z * d, sv.w * d);

    int i = s;
    for (; i + 1 < e; i += 2) {                   // unroll-2 for gather MLP
        int j0 = g_csrc[i];
        int j1 = g_csrc[i + 1];
        float d0 = g_dinv[j0];
        float d1 = g_dinv[j1];
        float4 v0 = G4[(size_t)j0 * 32 + lane];
        float4 v1 = G4[(size_t)j1 * 32 + lane];
        acc.x = fmaf(v0.x, d0, acc.x); acc.y = fmaf(v0.y, d0, acc.y);
        acc.z = fmaf(v0.z, d0, acc.z); acc.w = fmaf(v0.w, d0, acc.w);
        acc.x = fmaf(v1.x, d1, acc.x); acc.y = fmaf(v1.y, d1, acc.y);
        acc.z = fmaf(v1.z, d1, acc.z); acc.w = fmaf(v1.w, d1, acc.w);
    }
    if (i < e) {
        int j = g_csrc[i];
        float dj = g_dinv[j];
        float4 v = G4[(size_t)j * 32 + lane];
        acc.x = fmaf(v.x, dj, acc.x); acc.y = fmaf(v.y, dj, acc.y);
        acc.z = fmaf(v.z, dj, acc.z); acc.w = fmaf(v.w, dj, acc.w);
    }

    float4 b = ((const float4*)bias)[lane];
    acc.x = fmaxf(fmaf(acc.x, d, b.x), 0.f);
    acc.y = fmaxf(fmaf(acc.y, d, b.y), 0.f);
    acc.z = fmaxf(fmaf(acc.z, d, b.z), 0.f);
    acc.w = fmaxf(fmaf(acc.w, d, b.w), 0.f);
    if (has_resid) {
        float4 r = ((const float4*)resid)[self];
        acc.x += r.x; acc.y += r.y; acc.z += r.z; acc.w += r.w;
    }
    ((float4*)O)[self] = acc;
}

// ---------------- Output GEMM: out = S @ Wc + bc;  S:[n,128], Wc:[128,40] ----------------
__global__ __launch_bounds__(256) void gemm_out_kernel(const float* __restrict__ S,
                                                       const float* __restrict__ Wc,
                                                       const float* __restrict__ bc,
                                                       float* __restrict__ out, int n) {
    __shared__ float Ws[128][40];
    __shared__ float Ss[128][33];   // pad -> conflict-free column reads
    __shared__ float bs[40];
    int t = threadIdx.x;
    int m0 = blockIdx.x * 128;
    for (int i = t; i < 128 * 40; i += 256) Ws[i / 40][i % 40] = Wc[i];
    if (t < 40) bs[t] = bc[t];

    int c0 = t & 7;     // 5 cols: c0 + 8*j
    int rq = t >> 3;    // 4 rows: rq*4 .. +3
    float acc[4][5];
#pragma unroll
    for (int r = 0; r < 4; r++)
#pragma unroll
        for (int j = 0; j < 5; j++) acc[r][j] = 0.0f;

    for (int k0 = 0; k0 < 128; k0 += 32) {
        __syncthreads();
#pragma unroll
        for (int j = 0; j < 4; j++) {
            int flat = t * 16 + j * 4;
            int row = flat >> 5, kk = flat & 31;
            float4 v = make_float4(0.f, 0.f, 0.f, 0.f);
            if (m0 + row < n)
                v = *(const float4*)(S + (size_t)(m0 + row) * 128 + k0 + kk);
            Ss[row][kk + 0] = v.x;
            Ss[row][kk + 1] = v.y;
            Ss[row][kk + 2] = v.z;
            Ss[row][kk + 3] = v.w;
        }
        __syncthreads();
#pragma unroll 8
        for (int k = 0; k < 32; k++) {
            float w0 = Ws[k0 + k][c0];
            float w1 = Ws[k0 + k][c0 + 8];
            float w2 = Ws[k0 + k][c0 + 16];
            float w3 = Ws[k0 + k][c0 + 24];
            float w4 = Ws[k0 + k][c0 + 32];
#pragma unroll
            for (int r = 0; r < 4; r++) {
                float a = Ss[rq * 4 + r][k];
                acc[r][0] += a * w0;
                acc[r][1] += a * w1;
                acc[r][2] += a * w2;
                acc[r][3] += a * w3;
                acc[r][4] += a * w4;
            }
        }
    }
#pragma unroll
    for (int r = 0; r < 4; r++) {
        int row = m0 + rq * 4 + r;
        if (row < n) {
#pragma unroll
            for (int j = 0; j < 5; j++)
                out[(size_t)row * 40 + c0 + 8 * j] = acc[r][j] + bs[c0 + 8 * j];
        }
    }
}

// ---------------- launch ----------------
extern "C" void kernel_launch(void* const* d_in, const int* in_sizes, int n_in,
                              void* d_out, int out_size) {
    const float* x  = (const float*)d_in[0];
    const float* W1 = (const float*)d_in[1];
    const float* b1 = (const float*)d_in[2];
    const float* W2 = (const float*)d_in[3];
    const float* b2 = (const float*)d_in[4];
    const float* Wc = (const float*)d_in[5];
    const float* bc = (const float*)d_in[6];
    const int*   ei = (const int*)d_in[7];

    int N = in_sizes[0] / FDIM;
    int E = in_sizes[7] / 2;
    if (N > NMAX) N = NMAX;
    if (E > EMAX) E = EMAX;
    const int* src = ei;
    const int* dst = ei + E;

    float *G, *O;
    cudaGetSymbolAddress((void**)&G, g_bufG);
    cudaGetSymbolAddress((void**)&O, g_bufO);

    // Lazy one-time stream/event setup (host resources only; no device memory).
    static cudaStream_t s2 = nullptr;
    static cudaEvent_t ev_fork = nullptr, ev_join = nullptr;
    if (s2 == nullptr) {
        cudaStreamCreateWithFlags(&s2, cudaStreamNonBlocking);
        cudaEventCreateWithFlags(&ev_fork, cudaEventDisableTiming);
        cudaEventCreateWithFlags(&ev_join, cudaEventDisableTiming);
    }

    int gemm_grid = (N + 127) / 128;
    int agg_grid  = (N * 32 + 255) / 256;

    // Fork: CSR build (by dst) + degrees on side stream, concurrent with GEMM1.
    cudaEventRecord(ev_fork, 0);
    cudaStreamWaitEvent(s2, ev_fork, 0);
    zero_cnt_kernel<<<(N + 255) / 256, 256, 0, s2>>>(N);
    count_kernel<<<(E + 255) / 256, 256, 0, s2>>>(dst, E);
    scan_kernel<<<1, 1024, 0, s2>>>(N, E);
    place_kernel<<<(E + 255) / 256, 256, 0, s2>>>(src, dst, E);
    cudaEventRecord(ev_join, s2);

    // Layer 1 GEMM (independent of CSR/dinv): h1 = x @ W1
    gemm_nk128<<<gemm_grid, 256>>>(x, W1, G, N);

    // Join: aggregation needs both h1 and the CSR/dinv.
    cudaStreamWaitEvent(0, ev_join, 0);
    aggregate_kernel<<<agg_grid, 256>>>(G, b1, O, nullptr, 0, N);

    // Layer 2: h2 = out1 @ W2 ; s = relu(...) + out1 (in place)
    gemm_nk128<<<gemm_grid, 256>>>(O, W2, G, N);
    aggregate_kernel<<<agg_grid, 256>>>(G, b2, O, O, 1, N);

    // Output: out = s @ Wc + bc
    gemm_out_kernel<<<(N + 127) / 128, 256>>>(O, Wc, bc, (float*)d_out, N);
}

// round 8
// speedup vs baseline: 1.5480x; 1.5480x over previous
#include <cuda_runtime.h>
#include <math.h>
#include <stdint.h>

// Problem-size maxima (fixed by the dataset: N=100000, E=1600000, F=H=128, OUT=40)
#define NMAX 100000
#define EMAX 1600000
#define FDIM 128
#define SCAN_BS 2048                       // elements per scan block
#define NBLK_MAX ((NMAX + SCAN_BS - 1) / SCAN_BS)   // 49

// ---------------- scratch (static device globals; no allocation) ----------------
__device__ __align__(16) float g_bufG[(size_t)NMAX * FDIM];   // h = A@W (unscaled)
__device__ __align__(16) float g_bufO[(size_t)NMAX * FDIM];   // out1, then s = out2+out1
__device__ float g_dinv[NMAX];
__device__ __align__(16) int g_cnt[NMAX + 8];
__device__ __align__(16) int g_rowstart[NMAX + 8];
__device__ __align__(16) int g_cursor[NMAX + 8];
__device__ int   g_csrc[EMAX];
__device__ int   g_bsum[64];
__device__ int   g_boff[64];

// ---------------- packed fp32x2 helpers (sm_103a FFMA2 path) ----------------
__device__ __forceinline__ unsigned long long pack2_dup(float x) {
    unsigned long long r;
    asm("mov.b64 %0, {%1, %1};" : "=l"(r) : "f"(x));
    return r;
}
__device__ __forceinline__ void fma2(unsigned long long& d,
                                     unsigned long long a,
                                     unsigned long long b) {
    asm("fma.rn.f32x2 %0, %1, %2, %0;" : "+l"(d) : "l"(a), "l"(b));
}

// ---------------- CSR build ----------------
__global__ void zero_cnt_kernel(int n) {
    int i = blockIdx.x * blockDim.x + threadIdx.x;
    if (i < n + 8) g_cnt[i] = 0;   // include pad
}

__global__ void count_kernel(const int* __restrict__ dst, int e) {
    int i = blockIdx.x * blockDim.x + threadIdx.x;
    if (i < e) atomicAdd(&g_cnt[dst[i]], 1);
}

// Stage 1: per-block sums of counts (coalesced int4 loads). 256 thr, 2048 elems/block.
__global__ __launch_bounds__(256) void scan1_kernel(int n) {
    __shared__ int red[256];
    int b = blockIdx.x, t = threadIdx.x;
    int base = b * SCAN_BS + t * 8;
    int s = 0;
    if (base + 8 <= n) {
        int4 a = *(const int4*)&g_cnt[base];
        int4 c = *(const int4*)&g_cnt[base + 4];
        s = a.x + a.y + a.z + a.w + c.x + c.y + c.z + c.w;
    } else {
        for (int i = 0; i < 8; i++) {
            int idx = base + i;
            if (idx < n) s += g_cnt[idx];
        }
    }
    red[t] = s;
    __syncthreads();
    for (int off = 128; off > 0; off >>= 1) {
        if (t < off) red[t] += red[t + off];
        __syncthreads();
    }
    if (t == 0) g_bsum[b] = red[0];
}

// Stage 2: serial exclusive scan of <=49 block sums (trivial), set rowstart[n].
__global__ void scan2_kernel(int nb, int n, int e_total) {
    if (threadIdx.x == 0 && blockIdx.x == 0) {
        int acc = 0;
        for (int i = 0; i < nb; i++) {
            g_boff[i] = acc;
            acc += g_bsum[i];
        }
        g_rowstart[n] = e_total;
    }
}

// Stage 3: distribute — block-local scan + write rowstart/cursor/dinv (coalesced).
__global__ __launch_bounds__(256) void scan3_kernel(int n) {
    __shared__ int sh[256];
    int b = blockIdx.x, t = threadIdx.x;
    int base = b * SCAN_BS + t * 8;
    int loc[8];
    int s = 0;
    if (base + 8 <= n) {
        int4 a = *(const int4*)&g_cnt[base];
        int4 c = *(const int4*)&g_cnt[base + 4];
        loc[0] = a.x; loc[1] = a.y; loc[2] = a.z; loc[3] = a.w;
        loc[4] = c.x; loc[5] = c.y; loc[6] = c.z; loc[7] = c.w;
        s = a.x + a.y + a.z + a.w + c.x + c.y + c.z + c.w;
    } else {
#pragma unroll
        for (int i = 0; i < 8; i++) {
            int idx = base + i;
            loc[i] = (idx < n) ? g_cnt[idx] : 0;
            s += loc[i];
        }
    }
    sh[t] = s;
    __syncthreads();
    // Hillis-Steele inclusive scan over 256 thread sums
    for (int off = 1; off < 256; off <<= 1) {
        int v = (t >= off) ? sh[t - off] : 0;
        __syncthreads();
        sh[t] += v;
        __syncthreads();
    }
    int pre = g_boff[b] + ((t > 0) ? sh[t - 1] : 0);
    if (base + 8 <= n) {
        int rs[8];
        float dv[8];
#pragma unroll
        for (int i = 0; i < 8; i++) {
            rs[i] = pre;
            dv[i] = rsqrtf((float)(loc[i] + 1));
            pre += loc[i];
        }
        *(int4*)&g_rowstart[base]     = make_int4(rs[0], rs[1], rs[2], rs[3]);
        *(int4*)&g_rowstart[base + 4] = make_int4(rs[4], rs[5], rs[6], rs[7]);
        *(int4*)&g_cursor[base]       = make_int4(rs[0], rs[1], rs[2], rs[3]);
        *(int4*)&g_cursor[base + 4]   = make_int4(rs[4], rs[5], rs[6], rs[7]);
        *(float4*)&g_dinv[base]       = make_float4(dv[0], dv[1], dv[2], dv[3]);
        *(float4*)&g_dinv[base + 4]   = make_float4(dv[4], dv[5], dv[6], dv[7]);
    } else {
#pragma unroll
        for (int i = 0; i < 8; i++) {
            int idx = base + i;
            if (idx < n) {
                g_rowstart[idx] = pre;
                g_cursor[idx]   = pre;
                g_dinv[idx]     = rsqrtf((float)(loc[i] + 1));
                pre += loc[i];
            }
        }
    }
}

__global__ void place_kernel(const int* __restrict__ src, const int* __restrict__ dst, int e) {
    int i = blockIdx.x * blockDim.x + threadIdx.x;
    if (i < e) {
        int d = dst[i];
        int p = atomicAdd(&g_cursor[d], 1);
        g_csrc[p] = src[i];
    }
}

// ---------------- GEMM: C = A @ W;  A:[n,128], W:[128,128]  (pure GEMM) ----------------
// Tile: 128 rows x 128 cols, BK=16, 256 threads, 8x8 micro-tile, fp32x2 accumulators.
__global__ __launch_bounds__(256) void gemm_nk128(const float* __restrict__ A,
                                                  const float* __restrict__ W,
                                                  float* __restrict__ C, int n) {
    __shared__ float As[16][128];   // [k][row]  (transposed)
    __shared__ float Bs[16][128];   // [k][col]
    int m0 = blockIdx.x * 128;
    int t = threadIdx.x;
    int tr = (t >> 4) * 8;
    int tc = (t & 15) * 8;
    unsigned long long acc2[8][4];
#pragma unroll
    for (int r = 0; r < 8; r++)
#pragma unroll
        for (int c = 0; c < 4; c++) acc2[r][c] = 0ULL;

    for (int k0 = 0; k0 < 128; k0 += 16) {
#pragma unroll
        for (int j = 0; j < 2; j++) {
            int flat = t * 8 + j * 4;
            int row = flat >> 4, kk = flat & 15;
            float4 v = make_float4(0.f, 0.f, 0.f, 0.f);
            if (m0 + row < n)
                v = *(const float4*)(A + (size_t)(m0 + row) * 128 + k0 + kk);
            As[kk + 0][row] = v.x;
            As[kk + 1][row] = v.y;
            As[kk + 2][row] = v.z;
            As[kk + 3][row] = v.w;
        }
#pragma unroll
        for (int j = 0; j < 2; j++) {
            int flat = t * 8 + j * 4;
            int kr = flat >> 7, cc = flat & 127;
            *(float4*)&Bs[kr][cc] = *(const float4*)(W + (size_t)(k0 + kr) * 128 + cc);
        }
        __syncthreads();
#pragma unroll
        for (int k = 0; k < 16; k++) {
            float4 a0 = *(float4*)&As[k][tr];
            float4 a1 = *(float4*)&As[k][tr + 4];
            ulonglong2 b0 = *(ulonglong2*)&Bs[k][tc];
            ulonglong2 b1 = *(ulonglong2*)&Bs[k][tc + 4];
            float a[8] = {a0.x, a0.y, a0.z, a0.w, a1.x, a1.y, a1.z, a1.w};
#pragma unroll
            for (int r = 0; r < 8; r++) {
                unsigned long long ar = pack2_dup(a[r]);
                fma2(acc2[r][0], ar, b0.x);
                fma2(acc2[r][1], ar, b0.y);
                fma2(acc2[r][2], ar, b1.x);
                fma2(acc2[r][3], ar, b1.y);
            }
        }
        __syncthreads();
    }
#pragma unroll
    for (int r = 0; r < 8; r++) {
        int row = m0 + tr + r;
        if (row < n) {
            ulonglong2 s0; s0.x = acc2[r][0]; s0.y = acc2[r][1];
            ulonglong2 s1; s1.x = acc2[r][2]; s1.y = acc2[r][3];
            *(ulonglong2*)(C + (size_t)row * 128 + tc)     = s0;
            *(ulonglong2*)(C + (size_t)row * 128 + tc + 4) = s1;
        }
    }
}

// ---------------- Aggregation: warp per node (pull / gather), unroll-4 ----------------
// O[i] = relu( dinv[i] * ( sum_j h[j]*dinv[j]  +  h[i]*dinv[i] ) + bias )  [+ resid[i]]
__global__ __launch_bounds__(256) void aggregate_kernel(const float* __restrict__ G,
                                                        const float* __restrict__ bias,
                                                        float* O, const float* resid,
                                                        int has_resid, int n) {
    int warp = (blockIdx.x * blockDim.x + threadIdx.x) >> 5;
    int lane = threadIdx.x & 31;
    if (warp >= n) return;
    int s = g_rowstart[warp];
    int e = g_rowstart[warp + 1];
    const float4* G4 = (const float4*)G;
    size_t self = (size_t)warp * 32 + lane;
    float d = g_dinv[warp];
    float4 sv = G4[self];
    float4 acc = make_float4(sv.x * d, sv.y * d, sv.z * d, sv.w * d);

    int i = s;
    for (; i + 3 < e; i += 4) {              // batch 4 index loads -> 4 gathers in flight
        int j0 = g_csrc[i];
        int j1 = g_csrc[i + 1];
        int j2 = g_csrc[i + 2];
        int j3 = g_csrc[i + 3];
        float d0 = g_dinv[j0], d1 = g_dinv[j1], d2 = g_dinv[j2], d3 = g_dinv[j3];
        float4 v0 = G4[(size_t)j0 * 32 + lane];
        float4 v1 = G4[(size_t)j1 * 32 + lane];
        float4 v2 = G4[(size_t)j2 * 32 + lane];
        float4 v3 = G4[(size_t)j3 * 32 + lane];
        acc.x = fmaf(v0.x, d0, acc.x); acc.y = fmaf(v0.y, d0, acc.y);
        acc.z = fmaf(v0.z, d0, acc.z); acc.w = fmaf(v0.w, d0, acc.w);
        acc.x = fmaf(v1.x, d1, acc.x); acc.y = fmaf(v1.y, d1, acc.y);
        acc.z = fmaf(v1.z, d1, acc.z); acc.w = fmaf(v1.w, d1, acc.w);
        acc.x = fmaf(v2.x, d2, acc.x); acc.y = fmaf(v2.y, d2, acc.y);
        acc.z = fmaf(v2.z, d2, acc.z); acc.w = fmaf(v2.w, d2, acc.w);
        acc.x = fmaf(v3.x, d3, acc.x); acc.y = fmaf(v3.y, d3, acc.y);
        acc.z = fmaf(v3.z, d3, acc.z); acc.w = fmaf(v3.w, d3, acc.w);
    }
    for (; i < e; i++) {
        int j = g_csrc[i];
        float dj = g_dinv[j];
        float4 v = G4[(size_t)j * 32 + lane];
        acc.x = fmaf(v.x, dj, acc.x); acc.y = fmaf(v.y, dj, acc.y);
        acc.z = fmaf(v.z, dj, acc.z); acc.w = fmaf(v.w, dj, acc.w);
    }

    float4 b = ((const float4*)bias)[lane];
    acc.x = fmaxf(fmaf(acc.x, d, b.x), 0.f);
    acc.y = fmaxf(fmaf(acc.y, d, b.y), 0.f);
    acc.z = fmaxf(fmaf(acc.z, d, b.z), 0.f);
    acc.w = fmaxf(fmaf(acc.w, d, b.w), 0.f);
    if (has_resid) {
        float4 r = ((const float4*)resid)[self];
        acc.x += r.x; acc.y += r.y; acc.z += r.z; acc.w += r.w;
    }
    ((float4*)O)[self] = acc;
}

// ---------------- Output GEMM: out = S @ Wc + bc;  S:[n,128], Wc:[128,40] ----------------
__global__ __launch_bounds__(256) void gemm_out_kernel(const float* __restrict__ S,
                                                       const float* __restrict__ Wc,
                                                       const float* __restrict__ bc,
                                                       float* __restrict__ out, int n) {
    __shared__ float Ws[128][40];
    __shared__ float Ss[128][33];
    __shared__ float bs[40];
    int t = threadIdx.x;
    int m0 = blockIdx.x * 128;
    for (int i = t; i < 128 * 40; i += 256) Ws[i / 40][i % 40] = Wc[i];
    if (t < 40) bs[t] = bc[t];

    int c0 = t & 7;
    int rq = t >> 3;
    float acc[4][5];
#pragma unroll
    for (int r = 0; r < 4; r++)
#pragma unroll
        for (int j = 0; j < 5; j++) acc[r][j] = 0.0f;

    for (int k0 = 0; k0 < 128; k0 += 32) {
        __syncthreads();
#pragma unroll
        for (int j = 0; j < 4; j++) {
            int flat = t * 16 + j * 4;
            int row = flat >> 5, kk = flat & 31;
            float4 v = make_float4(0.f, 0.f, 0.f, 0.f);
            if (m0 + row < n)
                v = *(const float4*)(S + (size_t)(m0 + row) * 128 + k0 + kk);
            Ss[row][kk + 0] = v.x;
            Ss[row][kk + 1] = v.y;
            Ss[row][kk + 2] = v.z;
            Ss[row][kk + 3] = v.w;
        }
        __syncthreads();
#pragma unroll 8
        for (int k = 0; k < 32; k++) {
            float w0 = Ws[k0 + k][c0];
            float w1 = Ws[k0 + k][c0 + 8];
            float w2 = Ws[k0 + k][c0 + 16];
            float w3 = Ws[k0 + k][c0 + 24];
            float w4 = Ws[k0 + k][c0 + 32];
#pragma unroll
            for (int r = 0; r < 4; r++) {
                float a = Ss[rq * 4 + r][k];
                acc[r][0] += a * w0;
                acc[r][1] += a * w1;
                acc[r][2] += a * w2;
                acc[r][3] += a * w3;
                acc[r][4] += a * w4;
            }
        }
    }
#pragma unroll
    for (int r = 0; r < 4; r++) {
        int row = m0 + rq * 4 + r;
        if (row < n) {
#pragma unroll
            for (int j = 0; j < 5; j++)
                out[(size_t)row * 40 + c0 + 8 * j] = acc[r][j] + bs[c0 + 8 * j];
        }
    }
}

// ---------------- launch ----------------
extern "C" void kernel_launch(void* const* d_in, const int* in_sizes, int n_in,
                              void* d_out, int out_size) {
    const float* x  = (const float*)d_in[0];
    const float* W1 = (const float*)d_in[1];
    const float* b1 = (const float*)d_in[2];
    const float* W2 = (const float*)d_in[3];
    const float* b2 = (const float*)d_in[4];
    const float* Wc = (const float*)d_in[5];
    const float* bc = (const float*)d_in[6];
    const int*   ei = (const int*)d_in[7];

    int N = in_sizes[0] / FDIM;
    int E = in_sizes[7] / 2;
    if (N > NMAX) N = NMAX;
    if (E > EMAX) E = EMAX;
    const int* src = ei;
    const int* dst = ei + E;

    float *G, *O;
    cudaGetSymbolAddress((void**)&G, g_bufG);
    cudaGetSymbolAddress((void**)&O, g_bufO);

    static cudaStream_t s2 = nullptr;
    static cudaEvent_t ev_fork = nullptr, ev_join = nullptr;
    if (s2 == nullptr) {
        cudaStreamCreateWithFlags(&s2, cudaStreamNonBlocking);
        cudaEventCreateWithFlags(&ev_fork, cudaEventDisableTiming);
        cudaEventCreateWithFlags(&ev_join, cudaEventDisableTiming);
    }

    int gemm_grid = (N + 127) / 128;
    int agg_grid  = (N * 32 + 255) / 256;
    int nscanblk  = (N + SCAN_BS - 1) / SCAN_BS;

    // Fork: CSR build (by dst) on side stream, concurrent with GEMM1.
    cudaEventRecord(ev_fork, 0);
    cudaStreamWaitEvent(s2, ev_fork, 0);
    zero_cnt_kernel<<<(N + 8 + 255) / 256, 256, 0, s2>>>(N);
    count_kernel<<<(E + 255) / 256, 256, 0, s2>>>(dst, E);
    scan1_kernel<<<nscanblk, 256, 0, s2>>>(N);
    scan2_kernel<<<1, 32, 0, s2>>>(nscanblk, N, E);
    scan3_kernel<<<nscanblk, 256, 0, s2>>>(N);
    place_kernel<<<(E + 255) / 256, 256, 0, s2>>>(src, dst, E);
    cudaEventRecord(ev_join, s2);

    // Layer 1 GEMM (independent of CSR/dinv): h1 = x @ W1
    gemm_nk128<<<gemm_grid, 256>>>(x, W1, G, N);

    // Join: aggregation needs both h1 and the CSR/dinv.
    cudaStreamWaitEvent(0, ev_join, 0);
    aggregate_kernel<<<agg_grid, 256>>>(G, b1, O, nullptr, 0, N);

    // Layer 2: h2 = out1 @ W2 ; s = relu(...) + out1 (in place)
    gemm_nk128<<<gemm_grid, 256>>>(O, W2, G, N);
    aggregate_kernel<<<agg_grid, 256>>>(G, b2, O, O, 1, N);

    // Output: out = s @ Wc + bc
    gemm_out_kernel<<<(N + 127) / 128, 256>>>(O, Wc, bc, (float*)d_out, N);
}